// round 10
// baseline (speedup 1.0000x reference)
#include <cuda_runtime.h>
#include <cstdint>

#define S_MAX   2146592
#define TPB     256
#define E       4
#define CHUNK   (TPB * E)
#define EPS_F   1e-8f

// ---------------- zeroed-each-launch block (single memset node) ----------------
struct Zeroed {
    unsigned h16a[65536];     // top-16-bit histogram
    unsigned h16b[65536];     // low-16-bit histogram (within median's top bin)
    double   base[4];         // sp, sg, spp, spg over all valid
    double   rsum[4];         // refit sums
    int      n, rn;
};
__device__ Zeroed   g_z;
__device__ unsigned g_resbits[S_MAX];
__device__ int      g_maskmode;     // 0=u8, 1=i32, 2=f32
__device__ unsigned g_p16;          // top-16 bits of median residual
__device__ long long g_krem2;       // remaining rank within the top bin
__device__ unsigned g_thbits;       // bits of threshold (nonneg-float order trick)
__device__ float    g_th;

// ---------------- helpers ----------------
template<int MODE>
__device__ __forceinline__ bool maskv(const void* m, int j) {
    if (MODE == 0) return ((const unsigned char*)m)[j] != 0;
    if (MODE == 1) return ((const int*)m)[j] != 0;
    return ((const float*)m)[j] != 0.0f;
}

__device__ __forceinline__ void affine_fit(double n, double sp, double sg,
                                           double spp, double spg,
                                           double& s, double& b) {
    double det = spp * n - sp * sp;
    if (fabs(det) >= 1e-8) {
        s = (spg * n - sp * sg) / det;
        b = (spp * sg - sp * spg) / det;
    } else {
        s = spg / fmax(spp, 1e-8);
        b = 0.0;
    }
}

// block-wide reduce of 4 floats + 1 int, then one fp64/int atomic set per block
__device__ __forceinline__ void block_sums(float sp, float sg, float spp, float spg,
                                           int n, double* dst, int* ndst) {
    __shared__ float s4[8][4];
    __shared__ int   sn[8];
    int t = threadIdx.x, lane = t & 31, wid = t >> 5;
#pragma unroll
    for (int o = 16; o; o >>= 1) {
        sp  += __shfl_down_sync(0xffffffffu, sp,  o);
        sg  += __shfl_down_sync(0xffffffffu, sg,  o);
        spp += __shfl_down_sync(0xffffffffu, spp, o);
        spg += __shfl_down_sync(0xffffffffu, spg, o);
    }
    n = __reduce_add_sync(0xffffffffu, n);
    if (lane == 0) {
        s4[wid][0] = sp; s4[wid][1] = sg; s4[wid][2] = spp; s4[wid][3] = spg;
        sn[wid] = n;
    }
    __syncthreads();
    if (wid == 0) {
        float v = s4[lane & 7][lane >> 3];
        v += __shfl_down_sync(0xffffffffu, v, 4);
        v += __shfl_down_sync(0xffffffffu, v, 2);
        v += __shfl_down_sync(0xffffffffu, v, 1);
        if ((lane & 7) == 0) atomicAdd(&dst[lane >> 3], (double)v);
    } else if (wid == 1) {
        int c = (lane < 8) ? sn[lane] : 0;
        c = __reduce_add_sync(0xffffffffu, c);
        if (lane == 0) atomicAdd(ndst, c);
    }
}

// ---------------- tiny: mask-format detect ----------------
__global__ void k_detect(const unsigned* __restrict__ m32, int S) {
    __shared__ unsigned cls[4];
    int t = threadIdx.x, lane = t & 31;
    if (t < 4) cls[t] = 0u;
    __syncthreads();
    unsigned c0 = 0, c1 = 0, c2 = 0, c3 = 0;
    int nw = (S < 16384 ? S : 16384) >> 2;
    for (int i = t; i < nw; i += TPB) {
        unsigned w = m32[i];
        c0 += (w & 0x000000FFu) ? 1u : 0u;
        c1 += (w & 0x0000FF00u) ? 1u : 0u;
        c2 += (w & 0x00FF0000u) ? 1u : 0u;
        c3 += (w & 0xFF000000u) ? 1u : 0u;
    }
    c0 = __reduce_add_sync(0xffffffffu, c0);
    c1 = __reduce_add_sync(0xffffffffu, c1);
    c2 = __reduce_add_sync(0xffffffffu, c2);
    c3 = __reduce_add_sync(0xffffffffu, c3);
    if (lane == 0) {
        if (c0) atomicAdd(&cls[0], c0);
        if (c1) atomicAdd(&cls[1], c1);
        if (c2) atomicAdd(&cls[2], c2);
        if (c3) atomicAdd(&cls[3], c3);
    }
    __syncthreads();
    if (t == 0) {
        int mode;
        if (cls[0] && cls[1])      mode = 0;   // u8: all byte offsets populated
        else if (cls[2] || cls[3]) mode = 2;   // f32 1.0f -> bytes 2,3
        else                       mode = 1;   // i32 0/1 -> byte 0 only
        g_maskmode = mode;
    }
}

// ---------------- pass 1: base sums over all valid ----------------
template<int MODE>
__device__ __forceinline__ void base_body(
    const float* __restrict__ pred, const float* __restrict__ gt,
    const void* __restrict__ mask, int S) {
    int t = threadIdx.x, b = blockIdx.x * CHUNK;
    float sp = 0.f, sg = 0.f, spp = 0.f, spg = 0.f; int n = 0;
#pragma unroll
    for (int e = 0; e < E; e++) {
        int j = b + e * TPB + t;
        if (j < S) {
            float p = pred[j], g = gt[j];
            if (maskv<MODE>(mask, j) && g > EPS_F && p > EPS_F) {
                n++; sp += p; sg += g;
                spp = fmaf(p, p, spp); spg = fmaf(p, g, spg);
            }
        }
    }
    block_sums(sp, sg, spp, spg, n, g_z.base, &g_z.n);
}

__global__ void __launch_bounds__(TPB) k_base(
    const float* __restrict__ pred, const float* __restrict__ gt,
    const void* __restrict__ mask, int S) {
    int mode = g_maskmode;
    if (mode == 0)      base_body<0>(pred, gt, mask, S);
    else if (mode == 1) base_body<1>(pred, gt, mask, S);
    else                base_body<2>(pred, gt, mask, S);
}

// ---------------- pass 2: residual bits + top-16-bit histogram ----------------
template<int MODE>
__device__ __forceinline__ void h16a_body(
    const float* __restrict__ pred, const float* __restrict__ gt,
    const void* __restrict__ mask, int S, float s0, float b0) {
    int t = threadIdx.x, b = blockIdx.x * CHUNK;
#pragma unroll
    for (int e = 0; e < E; e++) {
        int j = b + e * TPB + t;
        if (j < S) {
            float p = pred[j], g = gt[j];
            bool v = maskv<MODE>(mask, j) && (g > EPS_F) && (p > EPS_F);
            float r = fabsf(g - fmaf(s0, p, b0));
            unsigned bits = v ? __float_as_uint(r) : 0xFFFFFFFFu;
            g_resbits[j] = bits;
            if (v) atomicAdd(&g_z.h16a[bits >> 16], 1u);   // invalids never histogrammed
        }
    }
}

__global__ void __launch_bounds__(TPB) k_hist16a(
    const float* __restrict__ pred, const float* __restrict__ gt,
    const void* __restrict__ mask, int S) {
    __shared__ float s_fit[2];
    if (threadIdx.x == 0) {     // base fit computed once per block (fp64 is expensive)
        double sd, bd;
        affine_fit((double)g_z.n, g_z.base[0], g_z.base[1], g_z.base[2], g_z.base[3], sd, bd);
        s_fit[0] = (float)sd; s_fit[1] = (float)bd;
    }
    __syncthreads();
    float s0 = s_fit[0], b0 = s_fit[1];
    int mode = g_maskmode;
    if (mode == 0)      h16a_body<0>(pred, gt, mask, S, s0, b0);
    else if (mode == 1) h16a_body<1>(pred, gt, mask, S, s0, b0);
    else                h16a_body<2>(pred, gt, mask, S, s0, b0);
}

// ---------------- tiny: rank-select within a 64K histogram ----------------
__global__ void k_scan16(int phase) {
    __shared__ unsigned csum[256];
    const unsigned* hist = (phase == 0) ? g_z.h16a : g_z.h16b;
    int t = threadIdx.x;
    unsigned s = 0;
    const unsigned* hp = hist + t * 256;
#pragma unroll 8
    for (int i = 0; i < 256; i++) s += hp[i];
    csum[t] = s;
    __syncthreads();
    if (t == 0) {
        long long rem = (phase == 0) ? (long long)(g_z.n - 1) / 2 : g_krem2;
        unsigned long long cum = 0;
        int C = 255;
        for (int c = 0; c < 256; c++) {
            unsigned v = csum[c];
            if ((long long)(cum + v) > rem) { C = c; break; }
            cum += v;
        }
        rem -= (long long)cum;
        const unsigned* cp = hist + C * 256;
        int B = 255; cum = 0;
        for (int i = 0; i < 256; i++) {
            unsigned v = cp[i];
            if ((long long)(cum + v) > rem) { B = i; break; }
            cum += v;
        }
        rem -= (long long)cum;
        unsigned bin = (unsigned)(C * 256 + B);
        if (phase == 0) {
            g_p16 = bin;
            g_krem2 = rem;
        } else {
            unsigned med_bits = (g_p16 << 16) | bin;
            float th = __uint_as_float(med_bits) * 1.5f;
            g_th = th;
            g_thbits = __float_as_uint(th);
        }
    }
}

// ---------------- pass 3: low-16-bit histogram of elements in the median's top bin ----------------
__global__ void __launch_bounds__(TPB) k_hist16b(int S) {
    int t = threadIdx.x, b = blockIdx.x * CHUNK;
    unsigned p16 = g_p16;
#pragma unroll
    for (int e = 0; e < E; e++) {
        int j = b + e * TPB + t;
        if (j < S) {
            unsigned bits = g_resbits[j];
            if ((bits >> 16) == p16)
                atomicAdd(&g_z.h16b[bits & 0xFFFFu], 1u);
        }
    }
}

// ---------------- pass 4: refit on inliers (resbits encodes validity + |r|) ----------------
__global__ void __launch_bounds__(TPB) k_refit(
    const float* __restrict__ pred, const float* __restrict__ gt, int S) {
    int t = threadIdx.x, b = blockIdx.x * CHUNK;
    unsigned thb = g_thbits;
    float sp = 0.f, sg = 0.f, spp = 0.f, spg = 0.f; int n = 0;
#pragma unroll
    for (int e = 0; e < E; e++) {
        int j = b + e * TPB + t;
        if (j < S) {
            if (g_resbits[j] < thb) {    // nonneg-float bits are order-preserving
                float p = pred[j], g = gt[j];
                n++; sp += p; sg += g;
                spp = fmaf(p, p, spp); spg = fmaf(p, g, spg);
            }
        }
    }
    block_sums(sp, sg, spp, spg, n, g_z.rsum, &g_z.rn);
}

// ---------------- pass 5: final fit (per block) + output ----------------
__global__ void __launch_bounds__(TPB) k_output(
    const float* __restrict__ pred, float* __restrict__ out, int S, int out_size) {
    __shared__ float s_fit[2];
    if (threadIdx.x == 0) {
        double sd, bd;
        affine_fit((double)g_z.rn, g_z.rsum[0], g_z.rsum[1], g_z.rsum[2], g_z.rsum[3], sd, bd);
        float scale, shiftv;
        if (g_z.rn > 10) { scale = (float)sd; shiftv = (float)bd; }
        else {
            double s0d, b0d;
            affine_fit((double)g_z.n, g_z.base[0], g_z.base[1], g_z.base[2], g_z.base[3], s0d, b0d);
            scale = (float)s0d; shiftv = (float)b0d;
        }
        s_fit[0] = fminf(fmaxf(scale, 0.01f), 100.f);
        s_fit[1] = shiftv;
    }
    __syncthreads();
    float scale = s_fit[0], shiftv = s_fit[1];
    int t = threadIdx.x, b = blockIdx.x * CHUNK;
#pragma unroll
    for (int e = 0; e < E; e++) {
        int j = b + e * TPB + t;
        if (j < S) out[j] = fmaxf(fmaf(scale, pred[j], shiftv), 0.f);
    }
    if (blockIdx.x == 0 && t == 0) {
        if (S < out_size)     out[S] = scale;
        if (S + 1 < out_size) out[S + 1] = shiftv;
    }
}

// ---------------- launch ----------------
extern "C" void kernel_launch(void* const* d_in, const int* in_sizes, int n_in,
                              void* d_out, int out_size) {
    const float* pred = (const float*)d_in[0];
    const float* gt   = (const float*)d_in[1];
    const void*  mask = d_in[2];
    float* out = (float*)d_out;
    int S = in_sizes[0];
    int NB = (S + CHUNK - 1) / CHUNK;

    void* zp = nullptr;
    cudaGetSymbolAddress(&zp, g_z);
    cudaMemsetAsync(zp, 0, sizeof(Zeroed));                 // 1 (memset node)

    k_detect<<<1, TPB>>>((const unsigned*)mask, S);         // 2
    k_base<<<NB, TPB>>>(pred, gt, mask, S);                 // 3
    k_hist16a<<<NB, TPB>>>(pred, gt, mask, S);              // 4  <- ncu slot
    k_scan16<<<1, TPB>>>(0);                                // 5
    k_hist16b<<<NB, TPB>>>(S);                              // 6
    k_scan16<<<1, TPB>>>(1);                                // 7
    k_refit<<<NB, TPB>>>(pred, gt, S);                      // 8
    k_output<<<NB, TPB>>>(pred, out, S, out_size);          // 9
}

// round 11
// speedup vs baseline: 5.0743x; 5.0743x over previous
#include <cuda_runtime.h>
#include <cstdint>

#define S_MAX   2146592
#define TPB     256
#define E       8
#define CHUNK   (TPB * E)
#define EPS_F   1e-8f

// ---------------- zeroed-each-launch block (single small memset node) ----------------
struct Zeroed {
    unsigned h0[256];        // hist of bits[31:24] (all elements; invalid -> bin 255)
    unsigned h1[256];        // hist of bits[23:16] within selected h0 bin
    unsigned h2[256];        // hist of bits[15:8]  within selected 16-bit prefix
    double   base[4];        // sp, sg, spp, spg over all valid
    double   rsum[4];        // refit sums
    int      n, rn;
};
__device__ Zeroed   g_z;
__device__ unsigned g_resbits[S_MAX];
__device__ int      g_maskmode;   // 0=u8, 1=i32, 2=f32

// ---------------- helpers ----------------
template<int MODE>
__device__ __forceinline__ bool maskv(const void* m, int j) {
    if (MODE == 0) return ((const unsigned char*)m)[j] != 0;
    if (MODE == 1) return ((const int*)m)[j] != 0;
    return ((const float*)m)[j] != 0.0f;
}

__device__ __forceinline__ void affine_fit(double n, double sp, double sg,
                                           double spp, double spg,
                                           double& s, double& b) {
    double det = spp * n - sp * sp;
    if (fabs(det) >= 1e-8) {
        s = (spg * n - sp * sg) / det;
        b = (spp * sg - sp * spg) / det;
    } else {
        s = spg / fmax(spp, 1e-8);
        b = 0.0;
    }
}

// block-wide reduce of 4 floats + 1 int, then one atomic per quantity per block
__device__ __forceinline__ void block_sums(float sp, float sg, float spp, float spg,
                                           int n, double* dst, int* ndst) {
    __shared__ float s4[8][4];
    __shared__ int   sn[8];
    int t = threadIdx.x, lane = t & 31, wid = t >> 5;
#pragma unroll
    for (int o = 16; o; o >>= 1) {
        sp  += __shfl_down_sync(0xffffffffu, sp,  o);
        sg  += __shfl_down_sync(0xffffffffu, sg,  o);
        spp += __shfl_down_sync(0xffffffffu, spp, o);
        spg += __shfl_down_sync(0xffffffffu, spg, o);
    }
    n = __reduce_add_sync(0xffffffffu, n);
    if (lane == 0) {
        s4[wid][0] = sp; s4[wid][1] = sg; s4[wid][2] = spp; s4[wid][3] = spg;
        sn[wid] = n;
    }
    __syncthreads();
    if (wid == 0) {
        float v = s4[lane & 7][lane >> 3];
        v += __shfl_down_sync(0xffffffffu, v, 4);
        v += __shfl_down_sync(0xffffffffu, v, 2);
        v += __shfl_down_sync(0xffffffffu, v, 1);
        if ((lane & 7) == 0) atomicAdd(&dst[lane >> 3], (double)v);
    } else if (wid == 1) {
        int c = (lane < 8) ? sn[lane] : 0;
        c = __reduce_add_sync(0xffffffffu, c);
        if (lane == 0) atomicAdd(ndst, c);
    }
}

// redundant per-block scan of one finalized 256-bin global histogram.
// All threads participate; result identical in every block (deterministic ints).
__device__ __forceinline__ void scan256(const unsigned* __restrict__ gh,
                                        long long& rem, unsigned& bin) {
    __shared__ unsigned s_h[256];
    __shared__ long long s_rem;
    __shared__ unsigned s_bin;
    int t = threadIdx.x;
    __syncthreads();                 // protect s_h reuse across calls
    s_h[t] = gh[t];
    __syncthreads();
    if (t == 0) {
        long long r = rem;
        unsigned long long cum = 0;
        int b = 255;
        for (int i = 0; i < 256; i++) {
            unsigned c = s_h[i];
            if ((long long)(cum + c) > r) { b = i; break; }
            cum += c;
        }
        s_bin = (unsigned)b;
        s_rem = r - (long long)cum;
    }
    __syncthreads();
    bin = s_bin;
    rem = s_rem;
}

// ---------------- node 2: mask detect + base sums ----------------
template<int MODE>
__device__ __forceinline__ void base_body(
    const float* __restrict__ pred, const float* __restrict__ gt,
    const void* __restrict__ mask, int S) {
    int t = threadIdx.x, b = blockIdx.x * CHUNK;
    float sp = 0.f, sg = 0.f, spp = 0.f, spg = 0.f; int n = 0;
#pragma unroll
    for (int e = 0; e < E; e++) {
        int j = b + e * TPB + t;
        if (j < S) {
            float p = pred[j], g = gt[j];
            if (maskv<MODE>(mask, j) && g > EPS_F && p > EPS_F) {
                n++; sp += p; sg += g;
                spp = fmaf(p, p, spp); spg = fmaf(p, g, spg);
            }
        }
    }
    block_sums(sp, sg, spp, spg, n, g_z.base, &g_z.n);
}

__global__ void __launch_bounds__(TPB) k_base(
    const float* __restrict__ pred, const float* __restrict__ gt,
    const void* __restrict__ mask, int S) {
    __shared__ unsigned s_cls[4];
    int t = threadIdx.x, lane = t & 31;
    // per-block redundant mask-format detect (first 16KB, L2-resident)
    if (t < 4) s_cls[t] = 0u;
    __syncthreads();
    {
        const unsigned* m32 = (const unsigned*)mask;
        unsigned c0 = 0, c1 = 0, c2 = 0, c3 = 0;
        int nw = (S < 16384 ? S : 16384) >> 2;
        for (int i = t; i < nw; i += TPB) {
            unsigned w = m32[i];
            c0 += (w & 0x000000FFu) ? 1u : 0u;
            c1 += (w & 0x0000FF00u) ? 1u : 0u;
            c2 += (w & 0x00FF0000u) ? 1u : 0u;
            c3 += (w & 0xFF000000u) ? 1u : 0u;
        }
        c0 = __reduce_add_sync(0xffffffffu, c0);
        c1 = __reduce_add_sync(0xffffffffu, c1);
        c2 = __reduce_add_sync(0xffffffffu, c2);
        c3 = __reduce_add_sync(0xffffffffu, c3);
        if (lane == 0) {
            if (c0) atomicAdd(&s_cls[0], c0);
            if (c1) atomicAdd(&s_cls[1], c1);
            if (c2) atomicAdd(&s_cls[2], c2);
            if (c3) atomicAdd(&s_cls[3], c3);
        }
        __syncthreads();
    }
    int mode;
    if (s_cls[0] && s_cls[1])      mode = 0;   // u8: all byte offsets populated
    else if (s_cls[2] || s_cls[3]) mode = 2;   // f32 1.0f -> bytes 2,3
    else                           mode = 1;   // i32 0/1 -> byte 0 only
    if (blockIdx.x == 0 && t == 0) g_maskmode = mode;

    if (mode == 0)      base_body<0>(pred, gt, mask, S);
    else if (mode == 1) base_body<1>(pred, gt, mask, S);
    else                base_body<2>(pred, gt, mask, S);
}

// ---------------- node 3: base fit (per block) + residual bits + hist level 0 ----------------
template<int MODE>
__device__ __forceinline__ void rb_body(
    const float* __restrict__ pred, const float* __restrict__ gt,
    const void* __restrict__ mask, int S, float s0, float b0, unsigned* s_h) {
    int t = threadIdx.x, b = blockIdx.x * CHUNK;
#pragma unroll
    for (int e = 0; e < E; e++) {
        int j = b + e * TPB + t;
        if (j < S) {
            float p = pred[j], g = gt[j];
            bool v = maskv<MODE>(mask, j) && (g > EPS_F) && (p > EPS_F);
            float r = fabsf(g - fmaf(s0, p, b0));
            unsigned bits = v ? __float_as_uint(r) : 0xFFFFFFFFu;
            g_resbits[j] = bits;
            atomicAdd(&s_h[bits >> 24], 1u);
        }
    }
}

__global__ void __launch_bounds__(TPB) k_resbits_hist0(
    const float* __restrict__ pred, const float* __restrict__ gt,
    const void* __restrict__ mask, int S) {
    __shared__ unsigned s_h[256];
    __shared__ float s_fit[2];
    int t = threadIdx.x;
    s_h[t] = 0u;
    if (t == 0) {   // base fit once per block (fp64 is expensive per-thread)
        double sd, bd;
        affine_fit((double)g_z.n, g_z.base[0], g_z.base[1], g_z.base[2], g_z.base[3], sd, bd);
        s_fit[0] = (float)sd; s_fit[1] = (float)bd;
    }
    __syncthreads();
    float s0 = s_fit[0], b0 = s_fit[1];
    int mode = g_maskmode;
    if (mode == 0)      rb_body<0>(pred, gt, mask, S, s0, b0, s_h);
    else if (mode == 1) rb_body<1>(pred, gt, mask, S, s0, b0, s_h);
    else                rb_body<2>(pred, gt, mask, S, s0, b0, s_h);
    __syncthreads();
    if (s_h[t]) atomicAdd(&g_z.h0[t], s_h[t]);
}

// ---------------- node 4: hist level 1 (scan h0 redundantly per block) ----------------
__global__ void __launch_bounds__(TPB) k_hist1(int S) {
    __shared__ unsigned s_h[256];
    int t = threadIdx.x;
    long long rem = ((long long)g_z.n - 1) / 2;   // lower median rank
    unsigned b0;
    scan256(g_z.h0, rem, b0);
    __syncthreads();
    s_h[t] = 0u;
    __syncthreads();
    int b = blockIdx.x * CHUNK;
#pragma unroll
    for (int e = 0; e < E; e++) {
        int j = b + e * TPB + t;
        if (j < S) {
            unsigned bits = g_resbits[j];
            if ((bits >> 24) == b0)
                atomicAdd(&s_h[(bits >> 16) & 255u], 1u);
        }
    }
    __syncthreads();
    if (s_h[t]) atomicAdd(&g_z.h1[t], s_h[t]);
}

// ---------------- node 5: hist level 2 (scan h0, h1 redundantly) ----------------
__global__ void __launch_bounds__(TPB) k_hist2(int S) {
    __shared__ unsigned s_h[256];
    int t = threadIdx.x;
    long long rem = ((long long)g_z.n - 1) / 2;
    unsigned b0, b1;
    scan256(g_z.h0, rem, b0);
    scan256(g_z.h1, rem, b1);
    unsigned p16 = (b0 << 8) | b1;
    __syncthreads();
    s_h[t] = 0u;
    __syncthreads();
    int b = blockIdx.x * CHUNK;
#pragma unroll
    for (int e = 0; e < E; e++) {
        int j = b + e * TPB + t;
        if (j < S) {
            unsigned bits = g_resbits[j];
            if ((bits >> 16) == p16)
                atomicAdd(&s_h[(bits >> 8) & 255u], 1u);
        }
    }
    __syncthreads();
    if (s_h[t]) atomicAdd(&g_z.h2[t], s_h[t]);
}

// ---------------- node 6: refit on inliers (scan h0,h1,h2 -> 24-bit median -> th) ----------------
__global__ void __launch_bounds__(TPB) k_refit(
    const float* __restrict__ pred, const float* __restrict__ gt, int S) {
    int t = threadIdx.x;
    long long rem = ((long long)g_z.n - 1) / 2;
    unsigned b0, b1, b2;
    scan256(g_z.h0, rem, b0);
    scan256(g_z.h1, rem, b1);
    scan256(g_z.h2, rem, b2);
    unsigned med_bits = (b0 << 24) | (b1 << 16) | (b2 << 8);   // 24-bit truncated median
    unsigned thbits = __float_as_uint(__uint_as_float(med_bits) * 1.5f);
    __syncthreads();

    int b = blockIdx.x * CHUNK;
    float sp = 0.f, sg = 0.f, spp = 0.f, spg = 0.f; int n = 0;
#pragma unroll
    for (int e = 0; e < E; e++) {
        int j = b + e * TPB + t;
        if (j < S) {
            if (g_resbits[j] < thbits) {   // nonneg-float bits are order-preserving
                float p = pred[j], g = gt[j];
                n++; sp += p; sg += g;
                spp = fmaf(p, p, spp); spg = fmaf(p, g, spg);
            }
        }
    }
    block_sums(sp, sg, spp, spg, n, g_z.rsum, &g_z.rn);
}

// ---------------- node 7: final fit (per block) + output ----------------
__global__ void __launch_bounds__(TPB) k_output(
    const float* __restrict__ pred, float* __restrict__ out, int S, int out_size) {
    __shared__ float s_fit[2];
    int t = threadIdx.x;
    if (t == 0) {
        double sd, bd;
        affine_fit((double)g_z.rn, g_z.rsum[0], g_z.rsum[1], g_z.rsum[2], g_z.rsum[3], sd, bd);
        float scale, shiftv;
        if (g_z.rn > 10) { scale = (float)sd; shiftv = (float)bd; }
        else {
            double s0d, b0d;
            affine_fit((double)g_z.n, g_z.base[0], g_z.base[1], g_z.base[2], g_z.base[3], s0d, b0d);
            scale = (float)s0d; shiftv = (float)b0d;
        }
        s_fit[0] = fminf(fmaxf(scale, 0.01f), 100.f);
        s_fit[1] = shiftv;
    }
    __syncthreads();
    float scale = s_fit[0], shiftv = s_fit[1];
    int b = blockIdx.x * CHUNK;
#pragma unroll
    for (int e = 0; e < E; e++) {
        int j = b + e * TPB + t;
        if (j < S) out[j] = fmaxf(fmaf(scale, pred[j], shiftv), 0.f);
    }
    if (blockIdx.x == 0 && t == 0) {
        if (S < out_size)     out[S] = scale;
        if (S + 1 < out_size) out[S + 1] = shiftv;
    }
}

// ---------------- launch (7 graph nodes) ----------------
extern "C" void kernel_launch(void* const* d_in, const int* in_sizes, int n_in,
                              void* d_out, int out_size) {
    const float* pred = (const float*)d_in[0];
    const float* gt   = (const float*)d_in[1];
    const void*  mask = d_in[2];
    float* out = (float*)d_out;
    int S = in_sizes[0];
    int NB = (S + CHUNK - 1) / CHUNK;

    void* zp = nullptr;
    cudaGetSymbolAddress(&zp, g_z);
    cudaMemsetAsync(zp, 0, sizeof(Zeroed));                  // 1

    k_base<<<NB, TPB>>>(pred, gt, mask, S);                  // 2
    k_resbits_hist0<<<NB, TPB>>>(pred, gt, mask, S);         // 3
    k_hist1<<<NB, TPB>>>(S);                                 // 4
    k_hist2<<<NB, TPB>>>(S);                                 // 5
    k_refit<<<NB, TPB>>>(pred, gt, S);                       // 6
    k_output<<<NB, TPB>>>(pred, out, S, out_size);           // 7
}